// round 10
// baseline (speedup 1.0000x reference)
#include <cuda_runtime.h>
#include <cuda_fp16.h>

#define NMAX 100000
#define EMAX 1250000
#define F 64

// Scratch (__device__ globals; no allocation allowed)
__device__ int   g_deg[NMAX];
__device__ int   g_rowtmp[NMAX];
__device__ int   g_rowptr[NMAX];     // after k_fill: row END (start+deg)
__device__ float g_dinv[NMAX];
__device__ float g_wsum[NMAX];       // wout_i = sum over outgoing edges of dinv[dst]
__device__ int   g_bsum[128];
__device__ int   g_csr[EMAX];
__device__ __align__(16) __half g_hsH[NMAX * F];  // layer-1 dinv-prescaled (fp16)
__device__ __align__(16) __half g_h1H[NMAX * F];  // relu(layer-1 out) (fp16)
__device__ float g_gsum[F];

// ---------------------------------------------------------------------------
// in-degree count, 8 edges per thread for ATOMG MLP
__global__ void k_deg(const int* __restrict__ dst, int e) {
    int t = blockIdx.x * blockDim.x + threadIdx.x;
    int stride = gridDim.x * blockDim.x;
    int i = t;
    for (; i + 7 * stride < e; i += 8 * stride) {
        int d[8];
        #pragma unroll
        for (int m = 0; m < 8; m++) d[m] = dst[i + m * stride];
        #pragma unroll
        for (int m = 0; m < 8; m++) atomicAdd(&g_deg[d[m]], 1);
    }
    for (; i < e; i += stride) atomicAdd(&g_deg[dst[i]], 1);
}

// scan pass 1 (1024 threads, shfl) + dinv + FUSED layer-1 GEMM (fp16 out)
__global__ void k_scan1_gemm1(const float* __restrict__ x, const float* __restrict__ W1, int n) {
    __shared__ int wsum[32];
    __shared__ float W1t[F][12];                   // W1t[j][k], row 48B
    int tid = threadIdx.x, lane = tid & 31, wid = tid >> 5;
    if (tid < F * 8) {
        int k = tid >> 6, j = tid & 63;
        W1t[j][k] = W1[tid];
    }
    int i = blockIdx.x * 1024 + tid;
    int v = (i < n) ? g_deg[i] : 0;
    int xsc = v;
    #pragma unroll
    for (int off = 1; off < 32; off <<= 1) {
        int t = __shfl_up_sync(0xffffffffu, xsc, off);
        if (lane >= off) xsc += t;
    }
    if (lane == 31) wsum[wid] = xsc;
    __syncthreads();
    if (wid == 0) {
        int y = wsum[lane];
        #pragma unroll
        for (int off = 1; off < 32; off <<= 1) {
            int t = __shfl_up_sync(0xffffffffu, y, off);
            if (lane >= off) y += t;
        }
        wsum[lane] = y;
    }
    __syncthreads();
    if (i < n) {
        g_rowtmp[i] = xsc - v + (wid > 0 ? wsum[wid - 1] : 0);
        float dinv = rsqrtf((float)(v + 1));
        g_dinv[i] = dinv;
        float4 xa = ((const float4*)x)[i * 2];
        float4 xb = ((const float4*)x)[i * 2 + 1];
        #pragma unroll
        for (int c = 0; c < 8; c++) {
            union { uint4 u; __half2 h[4]; } pk;
            #pragma unroll
            for (int m = 0; m < 4; m++) {
                float s[2];
                #pragma unroll
                for (int t = 0; t < 2; t++) {
                    int j = 8 * c + 2 * m + t;
                    float4 wa = *(const float4*)&W1t[j][0];
                    float4 wb = *(const float4*)&W1t[j][4];
                    s[t] = (xa.x*wa.x + xa.y*wa.y + xa.z*wa.z + xa.w*wa.w
                          + xb.x*wb.x + xb.y*wb.y + xb.z*wb.z + xb.w*wb.w) * dinv;
                }
                pk.h[m] = __floats2half2_rn(s[0], s[1]);
            }
            ((uint4*)g_hsH)[(size_t)i * 8 + c] = pk.u;
        }
    }
    if (tid == 0) g_bsum[blockIdx.x] = wsum[31];
}

// scan pass 2+3 fused: each block scans <=128 block sums (shfl), then applies
__global__ void k_scan23(int n, int nb) {
    __shared__ int wsum[4];
    __shared__ int boffs[128];
    int tid = threadIdx.x, lane = tid & 31, wid = tid >> 5;
    int v = 0, xv = 0;
    if (tid < 128) {
        v = (tid < nb) ? g_bsum[tid] : 0;
        xv = v;
        #pragma unroll
        for (int off = 1; off < 32; off <<= 1) {
            int t = __shfl_up_sync(0xffffffffu, xv, off);
            if (lane >= off) xv += t;
        }
        if (lane == 31) wsum[wid] = xv;
    }
    __syncthreads();
    if (tid < 128) {
        int base = 0;
        for (int w = 0; w < wid; w++) base += wsum[w];
        boffs[tid] = base + xv - v;                // exclusive
    }
    __syncthreads();
    int i = blockIdx.x * blockDim.x + tid;
    if (i < n) g_rowptr[i] = g_rowtmp[i] + boffs[i >> 10];
}

// CSR fill (advances g_rowptr to row END), 8 edges per thread for ATOMG MLP
__global__ void k_fill(const int* __restrict__ src, const int* __restrict__ dst, int e) {
    int t = blockIdx.x * blockDim.x + threadIdx.x;
    int stride = gridDim.x * blockDim.x;
    int i = t;
    for (; i + 7 * stride < e; i += 8 * stride) {
        int d[8], s[8], p[8];
        #pragma unroll
        for (int m = 0; m < 8; m++) d[m] = dst[i + m * stride];
        #pragma unroll
        for (int m = 0; m < 8; m++) s[m] = src[i + m * stride];
        #pragma unroll
        for (int m = 0; m < 8; m++) p[m] = atomicAdd(&g_rowptr[d[m]], 1);
        #pragma unroll
        for (int m = 0; m < 8; m++) g_csr[p[m]] = s[m];
    }
    for (; i < e; i += stride) {
        int p = atomicAdd(&g_rowptr[dst[i]], 1);
        g_csr[p] = src[i];
    }
}

// wout_i = sum over outgoing edges of dinv[dst]; 8-deep MLP
__global__ void k_wout(const int* __restrict__ src, const int* __restrict__ dst, int e) {
    int t = blockIdx.x * blockDim.x + threadIdx.x;
    int stride = gridDim.x * blockDim.x;
    int i = t;
    for (; i + 7 * stride < e; i += 8 * stride) {
        int d[8], s[8]; float dv[8];
        #pragma unroll
        for (int m = 0; m < 8; m++) d[m] = dst[i + m * stride];
        #pragma unroll
        for (int m = 0; m < 8; m++) s[m] = src[i + m * stride];
        #pragma unroll
        for (int m = 0; m < 8; m++) dv[m] = g_dinv[d[m]];
        #pragma unroll
        for (int m = 0; m < 8; m++) atomicAdd(&g_wsum[s[m]], dv[m]);
    }
    for (; i < e; i += stride) atomicAdd(&g_wsum[src[i]], g_dinv[dst[i]]);
}

// fp16 row-chunk accumulate: 8 halves (uint4) -> 4 float2
__device__ __forceinline__ void acc8(float2 a[4], uint4 v) {
    __half2* h = (__half2*)&v;
    #pragma unroll
    for (int m = 0; m < 4; m++) {
        float2 f = __half22float2(h[m]);
        a[m].x += f.x; a[m].y += f.y;
    }
}

// gather a node's in-edges into fp32 accumulators (8 lanes/node, lane=c)
__device__ __forceinline__ void gather_node(const uint4* __restrict__ hv,
                                            int rs, int d, int c, float2 a[4]) {
    int k = 0;
    for (; k + 4 <= d; k += 4) {
        int s0 = g_csr[rs + k],     s1 = g_csr[rs + k + 1];
        int s2 = g_csr[rs + k + 2], s3 = g_csr[rs + k + 3];
        uint4 v0 = hv[(size_t)s0 * 8 + c];
        uint4 v1 = hv[(size_t)s1 * 8 + c];
        uint4 v2 = hv[(size_t)s2 * 8 + c];
        uint4 v3 = hv[(size_t)s3 * 8 + c];
        acc8(a, v0); acc8(a, v1); acc8(a, v2); acc8(a, v3);
    }
    for (; k < d; k++) {
        uint4 v = hv[(size_t)g_csr[rs + k] * 8 + c];
        acc8(a, v);
    }
}

// layer-1 gather + relu -> h1 (fp16). NO smem: max occupancy for latency hiding.
__global__ void __launch_bounds__(256) k_gather1(const float* __restrict__ b1, int n) {
    int tid = threadIdx.x;
    int w = tid >> 5, lane = tid & 31;
    int grp = lane >> 3, c = lane & 7;
    int i = blockIdx.x * 32 + w * 4 + grp;
    if (i >= n) return;

    const uint4* hv = (const uint4*)g_hsH;
    int re = g_rowptr[i];                          // row end
    int d  = g_deg[i];
    int rs = re - d;
    float2 a[4];
    uint4 sv = hv[(size_t)i * 8 + c];              // self-loop
    {   __half2* h = (__half2*)&sv;
        #pragma unroll
        for (int m = 0; m < 4; m++) a[m] = __half22float2(h[m]); }
    gather_node(hv, rs, d, c, a);
    float dinv = g_dinv[i];
    union { uint4 u; __half2 h[4]; } pk;
    #pragma unroll
    for (int m = 0; m < 4; m++) {
        float2 bb = ((const float2*)b1)[4 * c + m];
        float r0 = fmaxf(fmaf(dinv, a[m].x, bb.x), 0.f);
        float r1 = fmaxf(fmaf(dinv, a[m].y, bb.y), 0.f);
        pk.h[m] = __floats2half2_rn(r0, r1);
    }
    ((uint4*)g_h1H)[(size_t)i * 8 + c] = pk.u;
}

// layer-2 GEMM + pooled reduction. Pool term per node: (h1@W2) * w_i where
// w_i = dinv_i*(dinv_i + wout_i). No hs2 store, no second gather.
__global__ void k_gemm2pool(const float* __restrict__ W2, int n) {
    __shared__ float W2s[F][68];                   // [k][j], padded row
    __shared__ float h1s[128][65];
    __shared__ float wts[128];
    __shared__ float bsum[F];
    int tid = threadIdx.x;
    for (int t = tid; t < F * F; t += 256) {
        int k = t >> 6, j = t & 63;
        W2s[k][j] = W2[t];
    }
    if (tid < F) bsum[tid] = 0.f;
    int base = blockIdx.x * 128;
    // coalesced h1 tile load: thread t handles (node t>>3, chunk t&7)
    for (int t = tid; t < 128 * 8; t += 256) {
        int nl = t >> 3, c = t & 7;
        int i = base + nl;
        uint4 u = (i < n) ? ((const uint4*)g_h1H)[(size_t)i * 8 + c]
                          : make_uint4(0, 0, 0, 0);
        __half2* h = (__half2*)&u;
        #pragma unroll
        for (int m = 0; m < 4; m++) {
            float2 f = __half22float2(h[m]);
            h1s[nl][8 * c + 2 * m]     = f.x;
            h1s[nl][8 * c + 2 * m + 1] = f.y;
        }
        if (c == 0) {
            float w = 0.f;
            if (i < n) {
                float dv = g_dinv[i];
                w = dv * (dv + g_wsum[i]);
            }
            wts[nl] = w;
        }
    }
    __syncthreads();

    int c2 = tid & 7, q = tid >> 3;
    int lane = tid & 31;
    float acc[4][8];
    #pragma unroll
    for (int r = 0; r < 4; r++)
        #pragma unroll
        for (int m = 0; m < 8; m++) acc[r][m] = 0.f;
    #pragma unroll 8
    for (int k = 0; k < F; k++) {
        float4 wa = *(const float4*)&W2s[k][8 * c2];
        float4 wb = *(const float4*)&W2s[k][8 * c2 + 4];
        #pragma unroll
        for (int r = 0; r < 4; r++) {
            float h = h1s[q * 4 + r][k];
            acc[r][0] = fmaf(h, wa.x, acc[r][0]);
            acc[r][1] = fmaf(h, wa.y, acc[r][1]);
            acc[r][2] = fmaf(h, wa.z, acc[r][2]);
            acc[r][3] = fmaf(h, wa.w, acc[r][3]);
            acc[r][4] = fmaf(h, wb.x, acc[r][4]);
            acc[r][5] = fmaf(h, wb.y, acc[r][5]);
            acc[r][6] = fmaf(h, wb.z, acc[r][6]);
            acc[r][7] = fmaf(h, wb.w, acc[r][7]);
        }
    }
    float w0 = wts[q * 4 + 0], w1 = wts[q * 4 + 1];
    float w2 = wts[q * 4 + 2], w3 = wts[q * 4 + 3];
    float part[8];
    #pragma unroll
    for (int m = 0; m < 8; m++) {
        part[m] = acc[0][m] * w0 + acc[1][m] * w1 + acc[2][m] * w2 + acc[3][m] * w3;
        // fold q-groups within the warp (lane bits 3,4 are q LSBs; c2 = lane&7)
        part[m] += __shfl_xor_sync(0xffffffffu, part[m], 8);
        part[m] += __shfl_xor_sync(0xffffffffu, part[m], 16);
    }
    if (lane < 8) {
        #pragma unroll
        for (int m = 0; m < 8; m++)
            atomicAdd(&bsum[8 * c2 + m], part[m]);
    }
    __syncthreads();
    if (tid < F) atomicAdd(&g_gsum[tid], bsum[tid]);
}

// head: g = gsum/n + b2 ; s = relu(state@Wm + bm) ; out = [g,s] @ Wc + bc
__global__ void k_final(const float* __restrict__ state, const float* __restrict__ Wm,
                        const float* __restrict__ bm, const float* __restrict__ Wc,
                        const float* __restrict__ bc, const float* __restrict__ b2,
                        float* __restrict__ out, int n) {
    __shared__ float c128[128];
    int j = threadIdx.x;                           // 128 threads
    if (j < 64) {
        c128[j] = g_gsum[j] / (float)n + b2[j];
    } else {
        int jj = j - 64;
        float s = bm[jj];
        #pragma unroll
        for (int k = 0; k < 8; k++) s += state[k] * Wm[k * 64 + jj];
        c128[j] = fmaxf(s, 0.f);
    }
    __syncthreads();
    if (j < 2) {
        float s = bc[j];
        for (int k = 0; k < 128; k++) s += c128[k] * Wc[k * 2 + j];
        out[j] = s;
    }
}

// ---------------------------------------------------------------------------
extern "C" void kernel_launch(void* const* d_in, const int* in_sizes, int n_in,
                              void* d_out, int out_size) {
    const float* x     = (const float*)d_in[0];
    const float* state = (const float*)d_in[1];
    const float* W1    = (const float*)d_in[2];
    const float* b1    = (const float*)d_in[3];
    const float* W2    = (const float*)d_in[4];
    const float* b2    = (const float*)d_in[5];
    const float* Wm    = (const float*)d_in[6];
    const float* bm    = (const float*)d_in[7];
    const float* Wc    = (const float*)d_in[8];
    const float* bc    = (const float*)d_in[9];
    const int*   ei    = (const int*)d_in[10];
    float* out         = (float*)d_out;

    int n = in_sizes[0] / 8;       // 100000
    int e = in_sizes[10] / 2;      // 1250000
    const int* src = ei;
    const int* dst = ei + e;

    int nb1 = (n + 1023) / 1024;   // 98 <= 128

    void* p_deg = nullptr; void* p_gsum = nullptr; void* p_wsum = nullptr;
    cudaGetSymbolAddress(&p_deg, g_deg);
    cudaGetSymbolAddress(&p_gsum, g_gsum);
    cudaGetSymbolAddress(&p_wsum, g_wsum);
    cudaMemsetAsync(p_deg, 0, (size_t)n * sizeof(int));
    cudaMemsetAsync(p_gsum, 0, F * sizeof(float));
    cudaMemsetAsync(p_wsum, 0, (size_t)n * sizeof(float));

    const int T = 256;
    k_deg<<<1184, T>>>(dst, e);
    k_scan1_gemm1<<<nb1, 1024>>>(x, W1, n);
    k_scan23<<<(n + T - 1) / T, T>>>(n, nb1);
    k_fill<<<1184, T>>>(src, dst, e);
    k_wout<<<1184, T>>>(src, dst, e);
    k_gather1<<<(n + 31) / 32, T>>>(b1, n);
    k_gemm2pool<<<(n + 127) / 128, T>>>(W2, n);
    k_final<<<1, 128>>>(state, Wm, bm, Wc, bc, b2, out, n);
}

// round 11
// speedup vs baseline: 1.2992x; 1.2992x over previous
#include <cuda_runtime.h>
#include <cuda_fp16.h>

#define NMAX 100000
#define EMAX 1250000
#define F 64

// Scratch (__device__ globals; no allocation allowed)
__device__ int   g_deg[NMAX];
__device__ int   g_rowtmp[NMAX];
__device__ int   g_rowptr[NMAX];     // after k_fill: row END (start+deg)
__device__ float g_dinv[NMAX];
__device__ int   g_bsum[128];
__device__ int   g_csr[EMAX];
__device__ __align__(16) __half g_hsH [NMAX * F];  // layer-1 dinv-prescaled (fp16)
__device__ __align__(16) __half g_h1H [NMAX * F];  // relu(layer-1 out) (fp16)
__device__ __align__(16) __half g_hs2H[NMAX * F];  // layer-2 dinv-prescaled (fp16)
__device__ float g_gsum[F];

// ---------------------------------------------------------------------------
// in-degree count, 8 edges per thread for ATOMG MLP
__global__ void k_deg(const int* __restrict__ dst, int e) {
    int t = blockIdx.x * blockDim.x + threadIdx.x;
    int stride = gridDim.x * blockDim.x;
    int i = t;
    for (; i + 7 * stride < e; i += 8 * stride) {
        int d[8];
        #pragma unroll
        for (int m = 0; m < 8; m++) d[m] = dst[i + m * stride];
        #pragma unroll
        for (int m = 0; m < 8; m++) atomicAdd(&g_deg[d[m]], 1);
    }
    for (; i < e; i += stride) atomicAdd(&g_deg[dst[i]], 1);
}

// scan pass 1 (1024 threads, shfl) + dinv + FUSED layer-1 GEMM (fp16 out)
__global__ void k_scan1_gemm1(const float* __restrict__ x, const float* __restrict__ W1, int n) {
    __shared__ int wsum[32];
    __shared__ float W1t[F][12];                   // W1t[j][k], row 48B
    int tid = threadIdx.x, lane = tid & 31, wid = tid >> 5;
    if (tid < F * 8) {
        int k = tid >> 6, j = tid & 63;
        W1t[j][k] = W1[tid];
    }
    int i = blockIdx.x * 1024 + tid;
    int v = (i < n) ? g_deg[i] : 0;
    int xsc = v;
    #pragma unroll
    for (int off = 1; off < 32; off <<= 1) {
        int t = __shfl_up_sync(0xffffffffu, xsc, off);
        if (lane >= off) xsc += t;
    }
    if (lane == 31) wsum[wid] = xsc;
    __syncthreads();
    if (wid == 0) {
        int y = wsum[lane];
        #pragma unroll
        for (int off = 1; off < 32; off <<= 1) {
            int t = __shfl_up_sync(0xffffffffu, y, off);
            if (lane >= off) y += t;
        }
        wsum[lane] = y;
    }
    __syncthreads();
    if (i < n) {
        g_rowtmp[i] = xsc - v + (wid > 0 ? wsum[wid - 1] : 0);
        float dinv = rsqrtf((float)(v + 1));
        g_dinv[i] = dinv;
        float4 xa = ((const float4*)x)[i * 2];
        float4 xb = ((const float4*)x)[i * 2 + 1];
        #pragma unroll
        for (int c = 0; c < 8; c++) {
            union { uint4 u; __half2 h[4]; } pk;
            #pragma unroll
            for (int m = 0; m < 4; m++) {
                float s[2];
                #pragma unroll
                for (int t = 0; t < 2; t++) {
                    int j = 8 * c + 2 * m + t;
                    float4 wa = *(const float4*)&W1t[j][0];
                    float4 wb = *(const float4*)&W1t[j][4];
                    s[t] = (xa.x*wa.x + xa.y*wa.y + xa.z*wa.z + xa.w*wa.w
                          + xb.x*wb.x + xb.y*wb.y + xb.z*wb.z + xb.w*wb.w) * dinv;
                }
                pk.h[m] = __floats2half2_rn(s[0], s[1]);
            }
            ((uint4*)g_hsH)[(size_t)i * 8 + c] = pk.u;
        }
    }
    if (tid == 0) g_bsum[blockIdx.x] = wsum[31];
}

// scan pass 2+3 fused: each block scans <=128 block sums (shfl), then applies
__global__ void k_scan23(int n, int nb) {
    __shared__ int wsum[4];
    __shared__ int boffs[128];
    int tid = threadIdx.x, lane = tid & 31, wid = tid >> 5;
    int v = 0, xv = 0;
    if (tid < 128) {
        v = (tid < nb) ? g_bsum[tid] : 0;
        xv = v;
        #pragma unroll
        for (int off = 1; off < 32; off <<= 1) {
            int t = __shfl_up_sync(0xffffffffu, xv, off);
            if (lane >= off) xv += t;
        }
        if (lane == 31) wsum[wid] = xv;
    }
    __syncthreads();
    if (tid < 128) {
        int base = 0;
        for (int w = 0; w < wid; w++) base += wsum[w];
        boffs[tid] = base + xv - v;                // exclusive
    }
    __syncthreads();
    int i = blockIdx.x * blockDim.x + tid;
    if (i < n) g_rowptr[i] = g_rowtmp[i] + boffs[i >> 10];
}

// CSR fill (advances g_rowptr to row END), 4 edges per thread (measured best)
__global__ void k_fill(const int* __restrict__ src, const int* __restrict__ dst, int e) {
    int t = blockIdx.x * blockDim.x + threadIdx.x;
    int stride = gridDim.x * blockDim.x;
    int i = t;
    for (; i + 3 * stride < e; i += 4 * stride) {
        int d0 = dst[i],              d1 = dst[i + stride];
        int d2 = dst[i + 2 * stride], d3 = dst[i + 3 * stride];
        int s0 = src[i],              s1 = src[i + stride];
        int s2 = src[i + 2 * stride], s3 = src[i + 3 * stride];
        int p0 = atomicAdd(&g_rowptr[d0], 1);
        int p1 = atomicAdd(&g_rowptr[d1], 1);
        int p2 = atomicAdd(&g_rowptr[d2], 1);
        int p3 = atomicAdd(&g_rowptr[d3], 1);
        g_csr[p0] = s0; g_csr[p1] = s1; g_csr[p2] = s2; g_csr[p3] = s3;
    }
    for (; i < e; i += stride) {
        int p = atomicAdd(&g_rowptr[dst[i]], 1);
        g_csr[p] = src[i];
    }
}

// fp16 row-chunk accumulate: 8 halves (uint4) -> 4 float2
__device__ __forceinline__ void acc8(float2 a[4], uint4 v) {
    __half2* h = (__half2*)&v;
    #pragma unroll
    for (int m = 0; m < 4; m++) {
        float2 f = __half22float2(h[m]);
        a[m].x += f.x; a[m].y += f.y;
    }
}

// gather a node's in-edges into fp32 accumulators (8 lanes/node, lane=c)
// 8-deep first batch for MLP (avg degree ~12.5 -> one 8-batch + tail)
__device__ __forceinline__ void gather_node(const uint4* __restrict__ hv,
                                            int rs, int d, int c, float2 a[4]) {
    int k = 0;
    for (; k + 8 <= d; k += 8) {
        int s[8];
        #pragma unroll
        for (int m = 0; m < 8; m++) s[m] = g_csr[rs + k + m];
        uint4 v[8];
        #pragma unroll
        for (int m = 0; m < 8; m++) v[m] = hv[(size_t)s[m] * 8 + c];
        #pragma unroll
        for (int m = 0; m < 8; m++) acc8(a, v[m]);
    }
    if (k + 4 <= d) {
        int s0 = g_csr[rs + k],     s1 = g_csr[rs + k + 1];
        int s2 = g_csr[rs + k + 2], s3 = g_csr[rs + k + 3];
        uint4 v0 = hv[(size_t)s0 * 8 + c];
        uint4 v1 = hv[(size_t)s1 * 8 + c];
        uint4 v2 = hv[(size_t)s2 * 8 + c];
        uint4 v3 = hv[(size_t)s3 * 8 + c];
        acc8(a, v0); acc8(a, v1); acc8(a, v2); acc8(a, v3);
        k += 4;
    }
    for (; k < d; k++) {
        uint4 v = hv[(size_t)g_csr[rs + k] * 8 + c];
        acc8(a, v);
    }
}

// layer-1 gather + relu -> h1 (fp16). NO smem: max occupancy for latency hiding.
__global__ void __launch_bounds__(256) k_gather1(const float* __restrict__ b1, int n) {
    int tid = threadIdx.x;
    int w = tid >> 5, lane = tid & 31;
    int grp = lane >> 3, c = lane & 7;
    int i = blockIdx.x * 32 + w * 4 + grp;
    if (i >= n) return;

    const uint4* hv = (const uint4*)g_hsH;
    int re = g_rowptr[i];                          // row end
    int d  = g_deg[i];
    int rs = re - d;
    float2 a[4];
    uint4 sv = hv[(size_t)i * 8 + c];              // self-loop
    {   __half2* h = (__half2*)&sv;
        #pragma unroll
        for (int m = 0; m < 4; m++) a[m] = __half22float2(h[m]); }
    gather_node(hv, rs, d, c, a);
    float dinv = g_dinv[i];
    union { uint4 u; __half2 h[4]; } pk;
    #pragma unroll
    for (int m = 0; m < 4; m++) {
        float2 bb = ((const float2*)b1)[4 * c + m];
        float r0 = fmaxf(fmaf(dinv, a[m].x, bb.x), 0.f);
        float r1 = fmaxf(fmaf(dinv, a[m].y, bb.y), 0.f);
        pk.h[m] = __floats2half2_rn(r0, r1);
    }
    ((uint4*)g_h1H)[(size_t)i * 8 + c] = pk.u;
}

// layer-2 GEMM (register-blocked, coalesced): hs2 = (h1 @ W2) * dinv, fp16 out
__global__ void k_gemm2(const float* __restrict__ W2, int n) {
    __shared__ float W2s[F][68];                   // [k][j], padded row
    __shared__ float h1s[128][65];
    __shared__ float dvs[128];
    int tid = threadIdx.x;
    for (int t = tid; t < F * F; t += 256) {
        int k = t >> 6, j = t & 63;
        W2s[k][j] = W2[t];
    }
    int base = blockIdx.x * 128;
    for (int t = tid; t < 128 * 8; t += 256) {
        int nl = t >> 3, c = t & 7;
        int i = base + nl;
        uint4 u = (i < n) ? ((const uint4*)g_h1H)[(size_t)i * 8 + c]
                          : make_uint4(0, 0, 0, 0);
        __half2* h = (__half2*)&u;
        #pragma unroll
        for (int m = 0; m < 4; m++) {
            float2 f = __half22float2(h[m]);
            h1s[nl][8 * c + 2 * m]     = f.x;
            h1s[nl][8 * c + 2 * m + 1] = f.y;
        }
        if (c == 0) dvs[nl] = (i < n) ? g_dinv[i] : 0.f;
    }
    __syncthreads();

    int c2 = tid & 7, q = tid >> 3;
    float acc[4][8];
    #pragma unroll
    for (int r = 0; r < 4; r++)
        #pragma unroll
        for (int m = 0; m < 8; m++) acc[r][m] = 0.f;
    #pragma unroll 8
    for (int k = 0; k < F; k++) {
        float4 wa = *(const float4*)&W2s[k][8 * c2];
        float4 wb = *(const float4*)&W2s[k][8 * c2 + 4];
        #pragma unroll
        for (int r = 0; r < 4; r++) {
            float h = h1s[q * 4 + r][k];
            acc[r][0] = fmaf(h, wa.x, acc[r][0]);
            acc[r][1] = fmaf(h, wa.y, acc[r][1]);
            acc[r][2] = fmaf(h, wa.z, acc[r][2]);
            acc[r][3] = fmaf(h, wa.w, acc[r][3]);
            acc[r][4] = fmaf(h, wb.x, acc[r][4]);
            acc[r][5] = fmaf(h, wb.y, acc[r][5]);
            acc[r][6] = fmaf(h, wb.z, acc[r][6]);
            acc[r][7] = fmaf(h, wb.w, acc[r][7]);
        }
    }
    #pragma unroll
    for (int r = 0; r < 4; r++) {
        int nl = q * 4 + r;
        int i = base + nl;
        if (i < n) {
            float dinv = dvs[nl];
            union { uint4 u; __half2 h[4]; } pk;
            #pragma unroll
            for (int m = 0; m < 4; m++)
                pk.h[m] = __floats2half2_rn(acc[r][2 * m] * dinv, acc[r][2 * m + 1] * dinv);
            ((uint4*)g_hs2H)[(size_t)i * 8 + c2] = pk.u;
        }
    }
}

// layer-2 gather + mean-pool partials (b2 folded at head); exact-cover grid
__global__ void __launch_bounds__(256) k_agg2(int n) {
    __shared__ float bsum[F];
    int tid = threadIdx.x, w = tid >> 5, lane = tid & 31;
    int grp = lane >> 3, c = lane & 7;
    if (tid < F) bsum[tid] = 0.f;
    __syncthreads();

    const uint4* hv = (const uint4*)g_hs2H;
    float2 asum[4] = {{0,0},{0,0},{0,0},{0,0}};
    int i = blockIdx.x * 32 + w * 4 + grp;
    if (i < n) {
        int re = g_rowptr[i];
        int d  = g_deg[i];
        int rs = re - d;
        float2 a[4];
        uint4 sv = hv[(size_t)i * 8 + c];
        {   __half2* h = (__half2*)&sv;
            #pragma unroll
            for (int m = 0; m < 4; m++) a[m] = __half22float2(h[m]); }
        gather_node(hv, rs, d, c, a);
        float dinv = g_dinv[i];
        #pragma unroll
        for (int m = 0; m < 4; m++) {
            asum[m].x = dinv * a[m].x;
            asum[m].y = dinv * a[m].y;
        }
    }
    #pragma unroll
    for (int m = 0; m < 4; m++) {
        asum[m].x += __shfl_xor_sync(0xffffffffu, asum[m].x, 8);
        asum[m].y += __shfl_xor_sync(0xffffffffu, asum[m].y, 8);
        asum[m].x += __shfl_xor_sync(0xffffffffu, asum[m].x, 16);
        asum[m].y += __shfl_xor_sync(0xffffffffu, asum[m].y, 16);
    }
    if (grp == 0) {
        #pragma unroll
        for (int m = 0; m < 4; m++) {
            atomicAdd(&bsum[8 * c + 2 * m],     asum[m].x);
            atomicAdd(&bsum[8 * c + 2 * m + 1], asum[m].y);
        }
    }
    __syncthreads();
    if (tid < F) atomicAdd(&g_gsum[tid], bsum[tid]);
}

// head: g = gsum/n + b2 ; s = relu(state@Wm + bm) ; out = [g,s] @ Wc + bc
__global__ void k_final(const float* __restrict__ state, const float* __restrict__ Wm,
                        const float* __restrict__ bm, const float* __restrict__ Wc,
                        const float* __restrict__ bc, const float* __restrict__ b2,
                        float* __restrict__ out, int n) {
    __shared__ float c128[128];
    int j = threadIdx.x;                           // 128 threads
    if (j < 64) {
        c128[j] = g_gsum[j] / (float)n + b2[j];
    } else {
        int jj = j - 64;
        float s = bm[jj];
        #pragma unroll
        for (int k = 0; k < 8; k++) s += state[k] * Wm[k * 64 + jj];
        c128[j] = fmaxf(s, 0.f);
    }
    __syncthreads();
    if (j < 2) {
        float s = bc[j];
        for (int k = 0; k < 128; k++) s += c128[k] * Wc[k * 2 + j];
        out[j] = s;
    }
}

// ---------------------------------------------------------------------------
extern "C" void kernel_launch(void* const* d_in, const int* in_sizes, int n_in,
                              void* d_out, int out_size) {
    const float* x     = (const float*)d_in[0];
    const float* state = (const float*)d_in[1];
    const float* W1    = (const float*)d_in[2];
    const float* b1    = (const float*)d_in[3];
    const float* W2    = (const float*)d_in[4];
    const float* b2    = (const float*)d_in[5];
    const float* Wm    = (const float*)d_in[6];
    const float* bm    = (const float*)d_in[7];
    const float* Wc    = (const float*)d_in[8];
    const float* bc    = (const float*)d_in[9];
    const int*   ei    = (const int*)d_in[10];
    float* out         = (float*)d_out;

    int n = in_sizes[0] / 8;       // 100000
    int e = in_sizes[10] / 2;      // 1250000
    const int* src = ei;
    const int* dst = ei + e;

    int nb1 = (n + 1023) / 1024;   // 98 <= 128

    void* p_deg = nullptr; void* p_gsum = nullptr;
    cudaGetSymbolAddress(&p_deg, g_deg);
    cudaGetSymbolAddress(&p_gsum, g_gsum);
    cudaMemsetAsync(p_deg, 0, (size_t)n * sizeof(int));
    cudaMemsetAsync(p_gsum, 0, F * sizeof(float));

    const int T = 256;
    k_deg<<<1184, T>>>(dst, e);
    k_scan1_gemm1<<<nb1, 1024>>>(x, W1, n);
    k_scan23<<<(n + T - 1) / T, T>>>(n, nb1);
    k_fill<<<1184, T>>>(src, dst, e);
    k_gather1<<<(n + 31) / 32, T>>>(b1, n);
    k_gemm2<<<(n + 127) / 128, T>>>(W2, n);
    k_agg2<<<(n + 31) / 32, T>>>(n);
    k_final<<<1, 128>>>(state, Wm, bm, Wc, bc, b2, out, n);
}